// round 4
// baseline (speedup 1.0000x reference)
#include <cuda_runtime.h>
#include <cuda_bf16.h>

// Problem constants (fixed for this problem instance)
#define NN 50000      // nodes
#define EE 800000     // edges
#define KD 256        // input feature dim (NIN)
#define HH 8          // heads
#define HC 256        // heads * channels (output dim)
// C = 32 channels per head; 1/sqrt(32):
#define RSQRT_C 0.17677669529663687f

// ---------------------------------------------------------------------------
// Scratch (device globals; no allocation allowed)
// ---------------------------------------------------------------------------
__device__ __align__(16) float g_Q[NN * HC];
__device__ __align__(16) float g_K[NN * HC];
__device__ __align__(16) float g_V[NN * HC];
__device__ __align__(16) float g_acc[NN * HC];   // unnormalized sum of exp(a)*v_j
__device__ float g_den[NN * HH];                 // sum of exp(a) per (node, head)
__device__ int   g_idx64;                        // 1 if edge_index buffer is int64
__device__ int   g_src[EE];
__device__ int   g_dst[EE];

// ---------------------------------------------------------------------------
// Vectorized global reduction (sm_90+): red.global.add.v4.f32
// ---------------------------------------------------------------------------
__device__ __forceinline__ void red_add_v4(float* p, float4 v) {
    asm volatile("red.global.add.v4.f32 [%0], {%1,%2,%3,%4};"
                 :: "l"(p), "f"(v.x), "f"(v.y), "f"(v.z), "f"(v.w)
                 : "memory");
}

// ---------------------------------------------------------------------------
// Detect edge_index element width. Values are in [0, 50000). If the buffer is
// little-endian int64, every odd int32 word is a zero high-word. If int32, the
// odd words are independent random indices (all-zero prob ~ (2e-5)^64 ~= 0).
// ---------------------------------------------------------------------------
__global__ void detect_kernel(const int* __restrict__ ei32) {
    if (threadIdx.x == 0) {
        int nz = 0;
#pragma unroll
        for (int i = 0; i < 64; i++) nz |= ei32[2 * i + 1];
        g_idx64 = (nz == 0) ? 1 : 0;
    }
}

// Normalize indices to int32 device arrays (in-bounds under either dtype).
__global__ void extract_kernel(const void* __restrict__ ei) {
    int e = blockIdx.x * 256 + threadIdx.x;
    if (e >= EE) return;
    if (g_idx64) {
        const long long* p = (const long long*)ei;
        g_src[e] = (int)p[e];
        g_dst[e] = (int)p[EE + e];
    } else {
        const int* p = (const int*)ei;
        g_src[e] = p[e];
        g_dst[e] = p[EE + e];
    }
}

// ---------------------------------------------------------------------------
// Shared GEMM core: C_tile[64 x 256] = A[row0..row0+63, 0:256] @ W[256, 256]
// Block = 256 threads. Thread (te = tid%8, to = tid/8) accumulates
// rows te*8..te*8+7  x  cols to*8..to*8+7 into acc[8][8].
// EAs: transposed A chunk [16][68] (padded vs bank conflicts), Bs: W chunk [16][256].
// ---------------------------------------------------------------------------
__device__ __forceinline__ void gemm_tile(const float* __restrict__ A, int row0, int maxrow,
                                          const float* __restrict__ W,
                                          float (&acc)[8][8], float* EAs, float* Bs)
{
    const int tid = threadIdx.x;
    const int te  = tid & 7;
    const int to  = tid >> 3;

#pragma unroll
    for (int i = 0; i < 8; i++)
#pragma unroll
        for (int j = 0; j < 8; j++) acc[i][j] = 0.f;

#pragma unroll 1
    for (int kc = 0; kc < 16; ++kc) {
        const int kk0 = kc * 16;
        // --- load A chunk (64 rows x 16 k), transposed into EAs[k][row]
        {
            int r  = tid >> 2;
            int k4 = (tid & 3) * 4;
            int row = row0 + r;
            if (row > maxrow) row = maxrow;           // clamp (tail); stores guarded later
            float4 av = *(const float4*)(A + row * KD + kk0 + k4);
            EAs[(k4 + 0) * 68 + r] = av.x;
            EAs[(k4 + 1) * 68 + r] = av.y;
            EAs[(k4 + 2) * 68 + r] = av.z;
            EAs[(k4 + 3) * 68 + r] = av.w;
        }
        // --- load W chunk (16 rows x 256) into Bs
        {
            const float4* Wf4 = (const float4*)(W + kk0 * KD);
            float4* Bf4 = (float4*)Bs;
#pragma unroll
            for (int i = 0; i < 4; i++) Bf4[tid + i * 256] = Wf4[tid + i * 256];
        }
        __syncthreads();
#pragma unroll
        for (int kk = 0; kk < 16; ++kk) {
            float4 a0 = *(const float4*)(EAs + kk * 68 + te * 8);
            float4 a1 = *(const float4*)(EAs + kk * 68 + te * 8 + 4);
            float4 b0 = *(const float4*)(Bs + kk * 256 + to * 8);
            float4 b1 = *(const float4*)(Bs + kk * 256 + to * 8 + 4);
            float a[8] = {a0.x, a0.y, a0.z, a0.w, a1.x, a1.y, a1.z, a1.w};
            float b[8] = {b0.x, b0.y, b0.z, b0.w, b1.x, b1.y, b1.z, b1.w};
#pragma unroll
            for (int i = 0; i < 8; i++)
#pragma unroll
                for (int j = 0; j < 8; j++)
                    acc[i][j] = fmaf(a[i], b[j], acc[i][j]);
        }
        __syncthreads();
    }
}

// ---------------------------------------------------------------------------
// Zero the accumulators (graph replays must start clean)
// ---------------------------------------------------------------------------
__global__ void zero_kernel() {
    int idx = blockIdx.x * 256 + threadIdx.x;
    if (idx < NN * HC) g_acc[idx] = 0.f;
    int base = NN * HC;
    if (idx >= base && idx < base + NN * HH) g_den[idx - base] = 0.f;
}

// ---------------------------------------------------------------------------
// Q/K/V/skip projections: blockIdx.y selects which of the 4 GEMMs.
// skip (y==3) goes straight into d_out (also initializes the poisoned output).
// ---------------------------------------------------------------------------
__global__ void __launch_bounds__(256)
qkvs_kernel(const float* __restrict__ x,
            const float* Wq, const float* bq,
            const float* Wk, const float* bk,
            const float* Wv, const float* bv,
            const float* Ws, const float* bs,
            float* dout)
{
    __shared__ float EAs[16 * 68];
    __shared__ float Bs[16 * 256];

    const float* W; const float* bias; float* outp;
    switch (blockIdx.y) {
        case 0:  W = Wq; bias = bq; outp = g_Q;  break;
        case 1:  W = Wk; bias = bk; outp = g_K;  break;
        case 2:  W = Wv; bias = bv; outp = g_V;  break;
        default: W = Ws; bias = bs; outp = dout; break;
    }

    const int row0 = blockIdx.x * 64;
    float acc[8][8];
    gemm_tile(x, row0, NN - 1, W, acc, EAs, Bs);

    const int tid = threadIdx.x;
    const int te  = tid & 7;
    const int to  = tid >> 3;
    float bb[8];
#pragma unroll
    for (int j = 0; j < 8; j++) bb[j] = bias[to * 8 + j];

#pragma unroll
    for (int i = 0; i < 8; i++) {
        int row = row0 + te * 8 + i;
        if (row < NN) {
            float4 o0 = make_float4(acc[i][0] + bb[0], acc[i][1] + bb[1],
                                    acc[i][2] + bb[2], acc[i][3] + bb[3]);
            float4 o1 = make_float4(acc[i][4] + bb[4], acc[i][5] + bb[5],
                                    acc[i][6] + bb[6], acc[i][7] + bb[7]);
            *(float4*)(outp + row * HC + to * 8)     = o0;
            *(float4*)(outp + row * HC + to * 8 + 4) = o1;
        }
    }
}

// ---------------------------------------------------------------------------
// Edge kernel: per 64-edge tile, compute e = edge_attr @ We in registers,
// then attention. Warp w owns head w: lane layout puts, for each edge,
// its 32 head-channels in lanes {m, m+8, m+16, m+24} -> shfl_xor(8),(16) reduce.
// exp(alpha) without max-subtraction (|alpha| small); atomically accumulate
// exp*v_j into g_acc and exp into g_den; finalize divides.
// ---------------------------------------------------------------------------
__global__ void __launch_bounds__(256)
edge_kernel(const float* __restrict__ ea, const float* __restrict__ We)
{
    __shared__ float EAs[16 * 68];
    __shared__ float Bs[16 * 256];
    __shared__ int s_src[64];
    __shared__ int s_dst[64];

    const int tid  = threadIdx.x;
    const int row0 = blockIdx.x * 64;    // EE = 12500 * 64, no tail

    if (tid < 64) {
        s_src[tid] = g_src[row0 + tid];
        s_dst[tid] = g_dst[row0 + tid];
    }
    // visibility guaranteed by the first __syncthreads inside gemm_tile

    float acc[8][8];
    gemm_tile(ea, row0, EE - 1, We, acc, EAs, Bs);

    const int w  = tid >> 5;        // warp id == head id
    const int l  = tid & 31;
    const int te = tid & 7;
    const int tl = l >> 3;          // 0..3: which 8-channel slice of the head
    const int cbase = w * 32 + tl * 8;

#pragma unroll
    for (int i = 0; i < 8; i++) {
        const int eg  = te * 8 + i;             // edge within tile (matches acc row)
        const int src = s_src[eg];
        const int dst = s_dst[eg];

        const float4* qp = (const float4*)(g_Q + dst * HC + cbase);
        const float4* kp = (const float4*)(g_K + src * HC + cbase);
        float4 q0 = qp[0], q1 = qp[1];
        float4 k0 = kp[0], k1 = kp[1];

        float p = (k0.x + acc[i][0]) * q0.x + (k0.y + acc[i][1]) * q0.y
                + (k0.z + acc[i][2]) * q0.z + (k0.w + acc[i][3]) * q0.w
                + (k1.x + acc[i][4]) * q1.x + (k1.y + acc[i][5]) * q1.y
                + (k1.z + acc[i][6]) * q1.z + (k1.w + acc[i][7]) * q1.w;

        // reduce over the 4 lanes holding this edge's head channels
        p += __shfl_xor_sync(0xffffffffu, p, 8);
        p += __shfl_xor_sync(0xffffffffu, p, 16);

        float exv = __expf(p * RSQRT_C);

        if (tl == 0) atomicAdd(g_den + dst * HH + w, exv);

        const float4* vp = (const float4*)(g_V + src * HC + cbase);
        float4 v0 = vp[0], v1 = vp[1];
        float* op = g_acc + dst * HC + cbase;
        float4 r0 = make_float4(exv * (v0.x + acc[i][0]), exv * (v0.y + acc[i][1]),
                                exv * (v0.z + acc[i][2]), exv * (v0.w + acc[i][3]));
        float4 r1 = make_float4(exv * (v1.x + acc[i][4]), exv * (v1.y + acc[i][5]),
                                exv * (v1.z + acc[i][6]), exv * (v1.w + acc[i][7]));
        red_add_v4(op, r0);
        red_add_v4(op + 4, r1);
    }
}

// ---------------------------------------------------------------------------
// Finalize: out += acc / den  (den==0 -> isolated node, contribution 0)
// ---------------------------------------------------------------------------
__global__ void finalize_kernel(float* __restrict__ out) {
    int idx = blockIdx.x * 256 + threadIdx.x;
    if (idx < NN * HC) {
        int n = idx >> 8;
        int h = (idx & 255) >> 5;
        float den = g_den[n * HH + h];
        float add = (den > 0.f) ? g_acc[idx] / den : 0.f;
        out[idx] += add;
    }
}

// ---------------------------------------------------------------------------
// Launch
// ---------------------------------------------------------------------------
extern "C" void kernel_launch(void* const* d_in, const int* in_sizes, int n_in,
                              void* d_out, int out_size)
{
    (void)in_sizes; (void)n_in; (void)out_size;
    const float* x  = (const float*)d_in[0];
    const void*  ei = d_in[1];
    const float* ea = (const float*)d_in[2];
    const float* Wq = (const float*)d_in[3];
    const float* bq = (const float*)d_in[4];
    const float* Wk = (const float*)d_in[5];
    const float* bk = (const float*)d_in[6];
    const float* Wv = (const float*)d_in[7];
    const float* bv = (const float*)d_in[8];
    const float* We = (const float*)d_in[9];
    const float* Ws = (const float*)d_in[10];
    const float* bs = (const float*)d_in[11];
    float* out = (float*)d_out;

    detect_kernel<<<1, 32>>>((const int*)ei);
    extract_kernel<<<(EE + 255) / 256, 256>>>(ei);
    {
        int total = NN * HC + NN * HH;
        zero_kernel<<<(total + 255) / 256, 256>>>();
    }
    {
        dim3 grid((NN + 63) / 64, 4);
        qkvs_kernel<<<grid, 256>>>(x, Wq, bq, Wk, bk, Wv, bv, Ws, bs, out);
    }
    edge_kernel<<<EE / 64, 256>>>(ea, We);
    finalize_kernel<<<(NN * HC + 255) / 256, 256>>>(out);
}

// round 7
// speedup vs baseline: 1.0336x; 1.0336x over previous
#include <cuda_runtime.h>
#include <cuda_bf16.h>

// Problem constants (fixed for this problem instance)
#define NN 50000      // nodes
#define EE 800000     // edges
#define KD 256        // input feature dim (NIN)
#define HH 8          // heads
#define HC 256        // heads * channels (output dim)
// C = 32 channels per head; 1/sqrt(32):
#define RSQRT_C 0.17677669529663687f

// ---------------------------------------------------------------------------
// Scratch (device globals; no allocation allowed)
// ---------------------------------------------------------------------------
__device__ __align__(16) float g_Q[NN * HC];
__device__ __align__(16) float g_K[NN * HC];
__device__ __align__(16) float g_V[NN * HC];
__device__ __align__(16) float g_acc[NN * HC];   // unnormalized sum of exp(a)*v_j
__device__ float g_den[NN * HH];                 // sum of exp(a) per (node, head)
__device__ int   g_idx64;                        // 1 if edge_index buffer is int64
__device__ int   g_src[EE];
__device__ int   g_dst[EE];

// ---------------------------------------------------------------------------
// Packed fp32x2 helpers (Blackwell sm_100+: double-rate packed FP32 FMA)
// ---------------------------------------------------------------------------
__device__ __forceinline__ unsigned long long dup_f32(float x) {
    unsigned long long r;
    asm("mov.b64 %0, {%1, %1};" : "=l"(r) : "r"(__float_as_uint(x)));
    return r;
}
__device__ __forceinline__ void ffma2(unsigned long long& d,
                                      unsigned long long a, unsigned long long b) {
    asm("fma.rn.f32x2 %0, %1, %2, %0;" : "+l"(d) : "l"(a), "l"(b));
}
__device__ __forceinline__ float2 unpack_f32x2(unsigned long long v) {
    unsigned int lo, hi;
    asm("mov.b64 {%0, %1}, %2;" : "=r"(lo), "=r"(hi) : "l"(v));
    return make_float2(__uint_as_float(lo), __uint_as_float(hi));
}

// ---------------------------------------------------------------------------
// Vectorized global reduction (sm_90+): red.global.add.v4.f32
// ---------------------------------------------------------------------------
__device__ __forceinline__ void red_add_v4(float* p, float4 v) {
    asm volatile("red.global.add.v4.f32 [%0], {%1,%2,%3,%4};"
                 :: "l"(p), "f"(v.x), "f"(v.y), "f"(v.z), "f"(v.w)
                 : "memory");
}

// ---------------------------------------------------------------------------
// Detect edge_index element width. Values are in [0, 50000). If the buffer is
// little-endian int64, every odd int32 word is a zero high-word. If int32, the
// odd words are independent random indices (all-zero prob ~ (2e-5)^64 ~= 0).
// ---------------------------------------------------------------------------
__global__ void detect_kernel(const int* __restrict__ ei32) {
    if (threadIdx.x == 0) {
        int nz = 0;
#pragma unroll
        for (int i = 0; i < 64; i++) nz |= ei32[2 * i + 1];
        g_idx64 = (nz == 0) ? 1 : 0;
    }
}

// Normalize indices to int32 device arrays (in-bounds under either dtype).
__global__ void extract_kernel(const void* __restrict__ ei) {
    int e = blockIdx.x * 256 + threadIdx.x;
    if (e >= EE) return;
    if (g_idx64) {
        const long long* p = (const long long*)ei;
        g_src[e] = (int)p[e];
        g_dst[e] = (int)p[EE + e];
    } else {
        const int* p = (const int*)ei;
        g_src[e] = p[e];
        g_dst[e] = p[EE + e];
    }
}

// ---------------------------------------------------------------------------
// Shared GEMM core: C_tile[64 x 256] = A[row0..row0+63, 0:256] @ W[256, 256]
// Block = 256 threads. Thread (te = tid%8, to = tid/8) accumulates
// rows te*8..te*8+7  x  cols to*8..to*8+7.
// FFMA2 layout: acc2[ip][j] packs rows (2ip, 2ip+1) for column j; the a-pair
// loads directly as an 8-byte LDS from the transposed EAs tile (consecutive
// rows are contiguous), the b operand is dup-packed {b,b}.
// EAs: transposed A chunk [16][68] (padded vs bank conflicts), Bs: W chunk [16][256].
// Result is unpacked into accr[8][8] (row-major, same as the old layout).
// ---------------------------------------------------------------------------
__device__ __forceinline__ void gemm_tile(const float* __restrict__ A, int row0, int maxrow,
                                          const float* __restrict__ W,
                                          float (&accr)[8][8], float* EAs, float* Bs)
{
    const int tid = threadIdx.x;
    const int te  = tid & 7;
    const int to  = tid >> 3;

    unsigned long long acc2[4][8];
#pragma unroll
    for (int ip = 0; ip < 4; ip++)
#pragma unroll
        for (int j = 0; j < 8; j++) acc2[ip][j] = 0ULL;

#pragma unroll 1
    for (int kc = 0; kc < 16; ++kc) {
        const int kk0 = kc * 16;
        // --- load A chunk (64 rows x 16 k), transposed into EAs[k][row]
        {
            int r  = tid >> 2;
            int k4 = (tid & 3) * 4;
            int row = row0 + r;
            if (row > maxrow) row = maxrow;           // clamp (tail); stores guarded later
            float4 av = *(const float4*)(A + row * KD + kk0 + k4);
            EAs[(k4 + 0) * 68 + r] = av.x;
            EAs[(k4 + 1) * 68 + r] = av.y;
            EAs[(k4 + 2) * 68 + r] = av.z;
            EAs[(k4 + 3) * 68 + r] = av.w;
        }
        // --- load W chunk (16 rows x 256) into Bs
        {
            const float4* Wf4 = (const float4*)(W + kk0 * KD);
            float4* Bf4 = (float4*)Bs;
#pragma unroll
            for (int i = 0; i < 4; i++) Bf4[tid + i * 256] = Wf4[tid + i * 256];
        }
        __syncthreads();
#pragma unroll
        for (int kk = 0; kk < 16; ++kk) {
            // a-pairs: rows (te*8+2ip, te*8+2ip+1) packed; contiguous in EAs.
            const unsigned long long* ap =
                (const unsigned long long*)(EAs + kk * 68 + te * 8);
            unsigned long long a01 = ap[0];
            unsigned long long a23 = ap[1];
            unsigned long long a45 = ap[2];
            unsigned long long a67 = ap[3];
            float4 b0 = *(const float4*)(Bs + kk * 256 + to * 8);
            float4 b1 = *(const float4*)(Bs + kk * 256 + to * 8 + 4);
            unsigned long long bd[8];
            bd[0] = dup_f32(b0.x); bd[1] = dup_f32(b0.y);
            bd[2] = dup_f32(b0.z); bd[3] = dup_f32(b0.w);
            bd[4] = dup_f32(b1.x); bd[5] = dup_f32(b1.y);
            bd[6] = dup_f32(b1.z); bd[7] = dup_f32(b1.w);
#pragma unroll
            for (int j = 0; j < 8; j++) {
                ffma2(acc2[0][j], a01, bd[j]);
                ffma2(acc2[1][j], a23, bd[j]);
                ffma2(acc2[2][j], a45, bd[j]);
                ffma2(acc2[3][j], a67, bd[j]);
            }
        }
        __syncthreads();
    }

#pragma unroll
    for (int ip = 0; ip < 4; ip++)
#pragma unroll
        for (int j = 0; j < 8; j++) {
            float2 v = unpack_f32x2(acc2[ip][j]);
            accr[2 * ip + 0][j] = v.x;
            accr[2 * ip + 1][j] = v.y;
        }
}

// ---------------------------------------------------------------------------
// Zero the accumulators (graph replays must start clean)
// ---------------------------------------------------------------------------
__global__ void zero_kernel() {
    int idx = blockIdx.x * 256 + threadIdx.x;
    if (idx < NN * HC) g_acc[idx] = 0.f;
    int base = NN * HC;
    if (idx >= base && idx < base + NN * HH) g_den[idx - base] = 0.f;
}

// ---------------------------------------------------------------------------
// Q/K/V/skip projections: blockIdx.y selects which of the 4 GEMMs.
// skip (y==3) goes straight into d_out (also initializes the poisoned output).
// ---------------------------------------------------------------------------
__global__ void __launch_bounds__(256)
qkvs_kernel(const float* __restrict__ x,
            const float* Wq, const float* bq,
            const float* Wk, const float* bk,
            const float* Wv, const float* bv,
            const float* Ws, const float* bs,
            float* dout)
{
    __shared__ __align__(16) float EAs[16 * 68];
    __shared__ __align__(16) float Bs[16 * 256];

    const float* W; const float* bias; float* outp;
    switch (blockIdx.y) {
        case 0:  W = Wq; bias = bq; outp = g_Q;  break;
        case 1:  W = Wk; bias = bk; outp = g_K;  break;
        case 2:  W = Wv; bias = bv; outp = g_V;  break;
        default: W = Ws; bias = bs; outp = dout; break;
    }

    const int row0 = blockIdx.x * 64;
    float acc[8][8];
    gemm_tile(x, row0, NN - 1, W, acc, EAs, Bs);

    const int tid = threadIdx.x;
    const int te  = tid & 7;
    const int to  = tid >> 3;
    float bb[8];
#pragma unroll
    for (int j = 0; j < 8; j++) bb[j] = bias[to * 8 + j];

#pragma unroll
    for (int i = 0; i < 8; i++) {
        int row = row0 + te * 8 + i;
        if (row < NN) {
            float4 o0 = make_float4(acc[i][0] + bb[0], acc[i][1] + bb[1],
                                    acc[i][2] + bb[2], acc[i][3] + bb[3]);
            float4 o1 = make_float4(acc[i][4] + bb[4], acc[i][5] + bb[5],
                                    acc[i][6] + bb[6], acc[i][7] + bb[7]);
            *(float4*)(outp + row * HC + to * 8)     = o0;
            *(float4*)(outp + row * HC + to * 8 + 4) = o1;
        }
    }
}

// ---------------------------------------------------------------------------
// Edge kernel: per 64-edge tile, compute e = edge_attr @ We in registers,
// then attention. Warp w owns head w: lane layout puts, for each edge,
// its 32 head-channels in lanes {m, m+8, m+16, m+24} -> shfl_xor(8),(16) reduce.
// exp(alpha) without max-subtraction (|alpha| small); atomically accumulate
// exp*v_j into g_acc and exp into g_den; finalize divides.
// ---------------------------------------------------------------------------
__global__ void __launch_bounds__(256)
edge_kernel(const float* __restrict__ ea, const float* __restrict__ We)
{
    __shared__ __align__(16) float EAs[16 * 68];
    __shared__ __align__(16) float Bs[16 * 256];
    __shared__ int s_src[64];
    __shared__ int s_dst[64];

    const int tid  = threadIdx.x;
    const int row0 = blockIdx.x * 64;    // EE = 12500 * 64, no tail

    if (tid < 64) {
        s_src[tid] = g_src[row0 + tid];
        s_dst[tid] = g_dst[row0 + tid];
    }
    // visibility guaranteed by the first __syncthreads inside gemm_tile

    float acc[8][8];
    gemm_tile(ea, row0, EE - 1, We, acc, EAs, Bs);

    const int w  = tid >> 5;        // warp id == head id
    const int l  = tid & 31;
    const int te = tid & 7;
    const int tl = l >> 3;          // 0..3: which 8-channel slice of the head
    const int cbase = w * 32 + tl * 8;

#pragma unroll
    for (int i = 0; i < 8; i++) {
        const int eg  = te * 8 + i;             // edge within tile (matches acc row)
        const int src = s_src[eg];
        const int dst = s_dst[eg];

        const float4* qp = (const float4*)(g_Q + dst * HC + cbase);
        const float4* kp = (const float4*)(g_K + src * HC + cbase);
        float4 q0 = qp[0], q1 = qp[1];
        float4 k0 = kp[0], k1 = kp[1];

        float p = (k0.x + acc[i][0]) * q0.x + (k0.y + acc[i][1]) * q0.y
                + (k0.z + acc[i][2]) * q0.z + (k0.w + acc[i][3]) * q0.w
                + (k1.x + acc[i][4]) * q1.x + (k1.y + acc[i][5]) * q1.y
                + (k1.z + acc[i][6]) * q1.z + (k1.w + acc[i][7]) * q1.w;

        // reduce over the 4 lanes holding this edge's head channels
        p += __shfl_xor_sync(0xffffffffu, p, 8);
        p += __shfl_xor_sync(0xffffffffu, p, 16);

        float exv = __expf(p * RSQRT_C);

        if (tl == 0) atomicAdd(g_den + dst * HH + w, exv);

        const float4* vp = (const float4*)(g_V + src * HC + cbase);
        float4 v0 = vp[0], v1 = vp[1];
        float* op = g_acc + dst * HC + cbase;
        float4 r0 = make_float4(exv * (v0.x + acc[i][0]), exv * (v0.y + acc[i][1]),
                                exv * (v0.z + acc[i][2]), exv * (v0.w + acc[i][3]));
        float4 r1 = make_float4(exv * (v1.x + acc[i][4]), exv * (v1.y + acc[i][5]),
                                exv * (v1.z + acc[i][6]), exv * (v1.w + acc[i][7]));
        red_add_v4(op, r0);
        red_add_v4(op + 4, r1);
    }
}

// ---------------------------------------------------------------------------
// Finalize: out += acc / den  (den==0 -> isolated node, contribution 0)
// ---------------------------------------------------------------------------
__global__ void finalize_kernel(float* __restrict__ out) {
    int idx = blockIdx.x * 256 + threadIdx.x;
    if (idx < NN * HC) {
        int n = idx >> 8;
        int h = (idx & 255) >> 5;
        float den = g_den[n * HH + h];
        float add = (den > 0.f) ? g_acc[idx] / den : 0.f;
        out[idx] += add;
    }
}

// ---------------------------------------------------------------------------
// Launch
// ---------------------------------------------------------------------------
extern "C" void kernel_launch(void* const* d_in, const int* in_sizes, int n_in,
                              void* d_out, int out_size)
{
    (void)in_sizes; (void)n_in; (void)out_size;
    const float* x  = (const float*)d_in[0];
    const void*  ei = d_in[1];
    const float* ea = (const float*)d_in[2];
    const float* Wq = (const float*)d_in[3];
    const float* bq = (const float*)d_in[4];
    const float* Wk = (const float*)d_in[5];
    const float* bk = (const float*)d_in[6];
    const float* Wv = (const float*)d_in[7];
    const float* bv = (const float*)d_in[8];
    const float* We = (const float*)d_in[9];
    const float* Ws = (const float*)d_in[10];
    const float* bs = (const float*)d_in[11];
    float* out = (float*)d_out;

    detect_kernel<<<1, 32>>>((const int*)ei);
    extract_kernel<<<(EE + 255) / 256, 256>>>(ei);
    {
        int total = NN * HC + NN * HH;
        zero_kernel<<<(total + 255) / 256, 256>>>();
    }
    {
        dim3 grid((NN + 63) / 64, 4);
        qkvs_kernel<<<grid, 256>>>(x, Wq, bq, Wk, bk, Wv, bv, Ws, bs, out);
    }
    edge_kernel<<<EE / 64, 256>>>(ea, We);
    finalize_kernel<<<(NN * HC + 255) / 256, 256>>>(out);
}